// round 2
// baseline (speedup 1.0000x reference)
#include <cuda_runtime.h>
#include <cstdint>

// ---------------------------------------------------------------------------
// UnionLayer: prefix-mask token compaction + broadcast add of node embedding.
//
// Outputs (concatenated float32 in d_out):
//   [0)              new_x    : (B, N*T, D)
//   [NX)             new_mask : (B, N*T)
//   [NX+BNT)         doclen   : (B,)
//   [NX+BNT+B)       new_tag  : (B, N*T)
//
// Because mask is a prefix mask, cumsum-based dest == seg_off[b,n] + t.
// ---------------------------------------------------------------------------

#define MAX_B   64
#define MAX_BN  8192
#define MAX_BNT (1 << 18)

__device__ int g_seg_off[MAX_BN + MAX_B];  // B * (N+1) exclusive offsets
__device__ int g_doclen[MAX_B];
__device__ int g_src[MAX_BNT];             // per output slot: flat src (n*T+t) or -1

// Kernel 1: per-batch inclusive scan of length -> exclusive seg offsets + doclen
__global__ void k_scan(const int* __restrict__ length, float* __restrict__ out_doclen, int N)
{
    int b = blockIdx.x;
    extern __shared__ int s[];
    int n = threadIdx.x;            // blockDim.x == N
    int v = length[b * N + n];
    s[n] = v;
    __syncthreads();
    for (int off = 1; off < N; off <<= 1) {
        int t = (n >= off) ? s[n - off] : 0;
        __syncthreads();
        s[n] += t;
        __syncthreads();
    }
    g_seg_off[b * (N + 1) + n + 1] = s[n];
    if (n == 0) g_seg_off[b * (N + 1)] = 0;
    if (n == N - 1) {
        g_doclen[b] = s[n];
        if (out_doclen) out_doclen[b] = (float)s[n];
    }
}

// Kernel 2: init src map, default tag (PAD=0), and new_mask
__global__ void k_init(float* __restrict__ mask_out, float* __restrict__ tag_out,
                       int NT, int total)
{
    int i = blockIdx.x * blockDim.x + threadIdx.x;
    if (i >= total) return;
    int b = i / NT;
    int j = i - b * NT;
    g_src[i] = -1;
    if (tag_out)  tag_out[i]  = 0.0f;
    if (mask_out) mask_out[i] = (j < g_doclen[b]) ? 1.0f : 0.0f;
}

// Kernel 3: scatter valid tokens -> src map (+ compacted tags).
// tags read as int32; if the buffer is actually int64, read the LE low word.
__global__ void k_scatter(const int* __restrict__ length,
                          const int* __restrict__ tags32,
                          float* __restrict__ tag_out,
                          int N, int T, int NT, int total, int tag_stride)
{
    int i = blockIdx.x * blockDim.x + threadIdx.x;
    if (i >= total) return;
    int b = i / NT;
    int r = i - b * NT;
    int n = r / T;
    int t = r - n * T;
    int len = length[b * N + n];
    if (t < len) {
        int dest = g_seg_off[b * (N + 1) + n] + t;
        int oi = b * NT + dest;
        g_src[oi] = r;                           // flat (n*T + t) within batch
        if (tag_out) tag_out[oi] = (float)tags32[(size_t)i * tag_stride];
    }
}

// Kernel 4: gather + broadcast add. One block per output row, float4 vectorized.
__global__ void k_main(const float4* __restrict__ x4,
                       const float4* __restrict__ gcn4,
                       float4* __restrict__ out4,
                       int N, int T, int NT, int Dv)
{
    int row = blockIdx.x;                       // row in [0, B*NT)
    int b = row / NT;
    int j = row - b * NT;
    int s = g_src[row];

    const float4* __restrict__ g = gcn4 + (size_t)(b * N + j / T) * Dv;
    float4* __restrict__ o = out4 + (size_t)row * Dv;

    if (s >= 0) {
        const float4* __restrict__ xr = x4 + ((size_t)b * NT + s) * Dv;
        for (int d = threadIdx.x; d < Dv; d += blockDim.x) {
            float4 gv = g[d];
            float4 xv = xr[d];
            gv.x += xv.x; gv.y += xv.y; gv.z += xv.z; gv.w += xv.w;
            o[d] = gv;
        }
    } else {
        for (int d = threadIdx.x; d < Dv; d += blockDim.x) {
            o[d] = g[d];
        }
    }
}

extern "C" void kernel_launch(void* const* d_in, const int* in_sizes, int n_in,
                              void* d_out, int out_size)
{
    const float* x      = (const float*)d_in[0];   // (B,N,T,D)
    const float* x_gcn  = (const float*)d_in[1];   // (B,N,D)
    // d_in[2] = mask (unused: mask is a prefix mask, equivalent to length)
    const int*   length = (const int*)d_in[3];     // (B,N)
    const int*   tags32 = (const int*)d_in[4];     // (B,N,T) as int32 (or int64 lo-words)

    const int NX  = in_sizes[0];          // B*N*T*D
    const int BN  = in_sizes[3];          // B*N
    const int BNT = in_sizes[2];          // B*N*T
    const int T   = BNT / BN;
    const int D   = in_sizes[1] / BN;

    // tags may be int32 (stride 1) or int64 viewed as int32 pairs (stride 2)
    const int tag_stride = (in_sizes[4] == 2 * BNT) ? 2 : 1;

    // Derive B from the full-concat output layout; fall back to new_x-only.
    int B = out_size - NX - 2 * BNT;
    bool full = (B >= 1 && B <= MAX_B && (BN % B) == 0);
    if (!full) {
        B = 8;
        if (BN % B) B = 1;
    }
    const int N  = BN / B;
    const int NT = N * T;

    float* out       = (float*)d_out;
    float* mask_out  = full ? out + NX             : nullptr;
    float* dlen_out  = full ? out + NX + BNT       : nullptr;
    float* tag_out   = full ? out + NX + BNT + B   : nullptr;

    // 1) segment offset scan (B blocks, N threads)
    k_scan<<<B, N, N * (int)sizeof(int)>>>(length, dlen_out, N);

    // 2) init src map + mask + default tags
    {
        int threads = 256;
        int blocks = (BNT + threads - 1) / threads;
        k_init<<<blocks, threads>>>(mask_out, tag_out, NT, BNT);
    }

    // 3) scatter valid tokens
    {
        int threads = 256;
        int blocks = (BNT + threads - 1) / threads;
        k_scatter<<<blocks, threads>>>(length, tags32, tag_out, N, T, NT, BNT, tag_stride);
    }

    // 4) gather + add (one block per output row)
    {
        int Dv = D / 4;
        k_main<<<BNT, 128>>>((const float4*)x, (const float4*)x_gcn,
                             (float4*)out, N, T, NT, Dv);
    }
}